// round 7
// baseline (speedup 1.0000x reference)
#include <cuda_runtime.h>
#include <cstdint>
#include <cfloat>

#define MAXN 50000
#define MAXE 1600000
#define NEG_SLOPE 0.2f
#define TILE 16

// Static scratch (no cudaMalloc allowed).
__device__ __align__(16) float g_hq[MAXN * 4];      // h_q          [N,4]
__device__ __align__(16) float g_kact[MAXN * 4];    // leaky(x@Wk.T)[N,4]
__device__ __align__(16) float g_qagg[MAXN * 4];    // segment_sum  [N,4]
__device__ __align__(16) float g_hproj[MAXN * 128]; // x@Wl.T + bl  [N,128]
__device__ int g_deg[MAXN];
__device__ int g_off[MAXN];                         // bucket start (unordered partition)
__device__ int g_cursor[MAXN];
__device__ int g_adj[MAXE];                         // col indices bucketed by row
__device__ int g_total;                             // global bucket cursor

__device__ __forceinline__ float leaky(float v) { return v >= 0.f ? v : NEG_SLOPE * v; }

// ---------------------------------------------------------------------------
// K0: zero degree counters + global cursor.
__global__ void k_init(int N) {
    int i = blockIdx.x * blockDim.x + threadIdx.x;
    if (i < N) g_deg[i] = 0;
    if (i == 0) g_total = 0;
}

// K1: count incoming edges per target node.
__global__ void k_deg(const int* __restrict__ row, int E) {
    int e = blockIdx.x * blockDim.x + threadIdx.x;
    if (e < E) atomicAdd(&g_deg[row[e]], 1);
}

// K2: unordered bucket allocation. Block-local smem scan + one global atomic
// per block. Buckets form a disjoint partition of [0,E); node order irrelevant.
__global__ void __launch_bounds__(256) k_off(int N) {
    __shared__ int sh[256];
    __shared__ int base;
    int t = threadIdx.x;
    int i = blockIdx.x * 256 + t;
    int d = (i < N) ? g_deg[i] : 0;
    sh[t] = d;
    __syncthreads();
    for (int o = 1; o < 256; o <<= 1) {
        int v = (t >= o) ? sh[t - o] : 0;
        __syncthreads();
        sh[t] += v;
        __syncthreads();
    }
    if (t == 255) base = atomicAdd(&g_total, sh[255]);
    __syncthreads();
    if (i < N) {
        int off = base + sh[t] - d;
        g_off[i] = off;
        g_cursor[i] = off;
    }
}

// K3: scatter col indices into row buckets.
__global__ void k_fill(const int* __restrict__ row, const int* __restrict__ col, int E) {
    int e = blockIdx.x * blockDim.x + threadIdx.x;
    if (e >= E) return;
    int p = atomicAdd(&g_cursor[row[e]], 1);
    g_adj[p] = col[e];
}

// ---------------------------------------------------------------------------
// K4: node projections. h_q = x@Wq.T, k_act = leaky(x@Wk.T), h_proj = x@Wl.T + bl.
__global__ void __launch_bounds__(128) k_proj(
    const float* __restrict__ x, const float* __restrict__ Wq,
    const float* __restrict__ Wk, const float* __restrict__ Wl,
    const float* __restrict__ bl, int N)
{
    __shared__ float xs[TILE * 132];
    int node0 = blockIdx.x * TILE;
    int tid = threadIdx.x;

    for (int i = tid; i < TILE * 32; i += 128) {
        int n = i >> 5, c = i & 31;
        float4 v = make_float4(0.f, 0.f, 0.f, 0.f);
        if (node0 + n < N)
            v = reinterpret_cast<const float4*>(x)[(size_t)(node0 + n) * 32 + c];
        *reinterpret_cast<float4*>(&xs[n * 132 + c * 4]) = v;
    }
    __syncthreads();

    int d = tid;
    float acc[TILE];
#pragma unroll
    for (int n = 0; n < TILE; n++) acc[n] = 0.f;
    const float4* Wl4 = reinterpret_cast<const float4*>(Wl);
    for (int k4 = 0; k4 < 32; k4++) {
        float4 w = Wl4[d * 32 + k4];
#pragma unroll
        for (int n = 0; n < TILE; n++) {
            float4 xv = *reinterpret_cast<const float4*>(&xs[n * 132 + k4 * 4]);
            acc[n] += w.x * xv.x + w.y * xv.y + w.z * xv.z + w.w * xv.w;
        }
    }
    float b = bl[d];
#pragma unroll
    for (int n = 0; n < TILE; n++) {
        int node = node0 + n;
        if (node < N) g_hproj[(size_t)node * 128 + d] = acc[n] + b;
    }

    {
        int isK = tid >= 64;
        int p = tid & 63;
        int n = p >> 2, h = p & 3;
        const float* W = isK ? Wk : Wq;
        float s = 0.f;
        for (int k = 0; k < 128; k++) s += xs[n * 132 + k] * W[h * 128 + k];
        int node = node0 + n;
        if (node < N) {
            if (isK) g_kact[node * 4 + h] = leaky(s);
            else     g_hq[node * 4 + h]   = s;
        }
    }
}

// ---------------------------------------------------------------------------
// K5: q_agg[r] = sum over incoming edges of h_q[col]. One warp per node.
__global__ void __launch_bounds__(256) k_node_qagg(int N) {
    int node = (blockIdx.x * blockDim.x + threadIdx.x) >> 5;
    int lane = threadIdx.x & 31;
    if (node >= N) return;
    int s0 = g_off[node], s1 = s0 + g_deg[node];
    float a0 = 0.f, a1 = 0.f, a2 = 0.f, a3 = 0.f;
    for (int i = s0 + lane; i < s1; i += 32) {
        int c = g_adj[i];
        float4 v = *reinterpret_cast<const float4*>(&g_hq[c * 4]);
        a0 += v.x; a1 += v.y; a2 += v.z; a3 += v.w;
    }
#pragma unroll
    for (int d = 16; d > 0; d >>= 1) {
        a0 += __shfl_xor_sync(0xffffffffu, a0, d);
        a1 += __shfl_xor_sync(0xffffffffu, a1, d);
        a2 += __shfl_xor_sync(0xffffffffu, a2, d);
        a3 += __shfl_xor_sync(0xffffffffu, a3, d);
    }
    if (lane == 0)
        *reinterpret_cast<float4*>(&g_qagg[node * 4]) = make_float4(a0, a1, a2, a3);
}

// ---------------------------------------------------------------------------
// Online softmax helpers: running (m, t) per head.
__device__ __forceinline__ void online_upd(float s, float& m, float& t) {
    if (s > m) { t = t * __expf(m - s) + 1.f; m = s; }
    else       { t += __expf(s - m); }
}
__device__ __forceinline__ void online_merge(float mo, float to, float& m, float& t) {
    float nm = fmaxf(m, mo);
    t = t * __expf(m - nm) + to * __expf(mo - nm);
    m = nm;
}

// K6: per-node softmax attention + output. One warp per node. Two sweeps:
//   sweep A: fused max + exp-sum via online softmax (one edge pass)
//   sweep B: alpha per edge + broadcast + coalesced h_proj gather/FMA
__global__ void __launch_bounds__(256) k_node_out(float* __restrict__ out, int N) {
    int node = (blockIdx.x * blockDim.x + threadIdx.x) >> 5;
    int lane = threadIdx.x & 31;
    if (node >= N) return;
    int s0 = g_off[node], s1 = s0 + g_deg[node];

    float4 kv = *reinterpret_cast<const float4*>(&g_kact[node * 4]);

    // sweep A: online (max, exp-sum) per head
    float m0 = -FLT_MAX, m1 = -FLT_MAX, m2 = -FLT_MAX, m3 = -FLT_MAX;
    float t0 = 0.f, t1 = 0.f, t2 = 0.f, t3 = 0.f;
    for (int i = s0 + lane; i < s1; i += 32) {
        int c = g_adj[i];
        float4 q = *reinterpret_cast<const float4*>(&g_qagg[c * 4]);
        online_upd(kv.x * q.x, m0, t0);
        online_upd(kv.y * q.y, m1, t1);
        online_upd(kv.z * q.z, m2, t2);
        online_upd(kv.w * q.w, m3, t3);
    }
#pragma unroll
    for (int d = 16; d > 0; d >>= 1) {
        online_merge(__shfl_xor_sync(0xffffffffu, m0, d), __shfl_xor_sync(0xffffffffu, t0, d), m0, t0);
        online_merge(__shfl_xor_sync(0xffffffffu, m1, d), __shfl_xor_sync(0xffffffffu, t1, d), m1, t1);
        online_merge(__shfl_xor_sync(0xffffffffu, m2, d), __shfl_xor_sync(0xffffffffu, t2, d), m2, t2);
        online_merge(__shfl_xor_sync(0xffffffffu, m3, d), __shfl_xor_sync(0xffffffffu, t3, d), m3, t3);
    }
    float i0 = 1.f / (t0 + 1e-8f);
    float i1 = 1.f / (t1 + 1e-8f);
    float i2 = 1.f / (t2 + 1e-8f);
    float i3 = 1.f / (t3 + 1e-8f);

    // sweep B: alpha_mean * h_proj[col] accumulate; lane owns out dims lane*4..+3
    float a0 = 0.f, a1 = 0.f, a2 = 0.f, a3 = 0.f;
    for (int base = s0; base < s1; base += 32) {
        int i = base + lane;
        float alpha = 0.f;
        int c = 0;
        if (i < s1) {
            c = g_adj[i];
            float4 q = *reinterpret_cast<const float4*>(&g_qagg[c * 4]);
            float e0 = __expf(kv.x * q.x - m0) * i0;
            float e1 = __expf(kv.y * q.y - m1) * i1;
            float e2 = __expf(kv.z * q.z - m2) * i2;
            float e3 = __expf(kv.w * q.w - m3) * i3;
            alpha = 0.25f * (e0 + e1 + e2 + e3);
        }
        int cnt = min(32, s1 - base);
#pragma unroll 4
        for (int j = 0; j < cnt; j++) {
            float aj = __shfl_sync(0xffffffffu, alpha, j);
            int   cj = __shfl_sync(0xffffffffu, c, j);
            float4 v = *reinterpret_cast<const float4*>(&g_hproj[(size_t)cj * 128 + lane * 4]);
            a0 += aj * v.x; a1 += aj * v.y; a2 += aj * v.z; a3 += aj * v.w;
        }
    }

    float4 r = make_float4(leaky(a0), leaky(a1), leaky(a2), leaky(a3));
    *reinterpret_cast<float4*>(&out[(size_t)node * 128 + lane * 4]) = r;
}

// ---------------------------------------------------------------------------
extern "C" void kernel_launch(void* const* d_in, const int* in_sizes, int n_in,
                              void* d_out, int out_size) {
    const float* x  = (const float*)d_in[0];
    const int*   ei = (const int*)d_in[1];
    const float* Wq = (const float*)d_in[2];
    const float* Wk = (const float*)d_in[3];
    const float* Wl = (const float*)d_in[4];
    const float* bl = (const float*)d_in[5];
    float* out = (float*)d_out;

    int N = in_sizes[0] / 128;
    int E = in_sizes[1] / 2;
    const int* row = ei;
    const int* col = ei + E;

    int eb = (E + 255) / 256;
    int nb = (N + 255) / 256;

    k_init<<<nb, 256>>>(N);
    k_proj<<<(N + TILE - 1) / TILE, 128>>>(x, Wq, Wk, Wl, bl, N);
    k_deg<<<eb, 256>>>(row, E);
    k_off<<<nb, 256>>>(N);
    k_fill<<<eb, 256>>>(row, col, E);

    int wb = (int)(((long long)N * 32 + 255) / 256);
    k_node_qagg<<<wb, 256>>>(N);
    k_node_out<<<wb, 256>>>(out, N);
}

// round 16
// speedup vs baseline: 1.1079x; 1.1079x over previous
#include <cuda_runtime.h>
#include <cstdint>
#include <cfloat>

#define MAXN 50000
#define MAXE 1600000
#define NEG_SLOPE 0.2f
#define TILE 16

// Static scratch (no cudaMalloc allowed).
__device__ __align__(16) float  g_hq[MAXN * 4];      // h_q          [N,4]
__device__ __align__(16) float  g_kact[MAXN * 4];    // leaky(x@Wk.T)[N,4]
__device__ __align__(16) float  g_qagg[MAXN * 4];    // segment_sum  [N,4]
__device__ __align__(16) float  g_hproj[MAXN * 128]; // x@Wl.T + bl  [N,128]
__device__ __align__(16) float4 g_sc[MAXE];          // per-edge scores -> exps
__device__ int g_deg[MAXN];
__device__ int g_off[MAXN];                          // bucket start (unordered partition)
__device__ int g_cursor[MAXN];
__device__ int g_adj[MAXE];                          // col indices bucketed by row
__device__ int g_total;                              // global bucket cursor

__device__ __forceinline__ float leaky(float v) { return v >= 0.f ? v : NEG_SLOPE * v; }

// ---------------------------------------------------------------------------
// K0: zero degree counters + global cursor.
__global__ void k_init(int N) {
    int i = blockIdx.x * blockDim.x + threadIdx.x;
    if (i < N) g_deg[i] = 0;
    if (i == 0) g_total = 0;
}

// K1: count incoming edges per target node.
__global__ void k_deg(const int* __restrict__ row, int E) {
    int e = blockIdx.x * blockDim.x + threadIdx.x;
    if (e < E) atomicAdd(&g_deg[row[e]], 1);
}

// K2: unordered bucket allocation. Block-local smem scan + one global atomic
// per block. Buckets form a disjoint partition of [0,E); node order irrelevant.
__global__ void __launch_bounds__(256) k_off(int N) {
    __shared__ int sh[256];
    __shared__ int base;
    int t = threadIdx.x;
    int i = blockIdx.x * 256 + t;
    int d = (i < N) ? g_deg[i] : 0;
    sh[t] = d;
    __syncthreads();
    for (int o = 1; o < 256; o <<= 1) {
        int v = (t >= o) ? sh[t - o] : 0;
        __syncthreads();
        sh[t] += v;
        __syncthreads();
    }
    if (t == 255) base = atomicAdd(&g_total, sh[255]);
    __syncthreads();
    if (i < N) {
        int off = base + sh[t] - d;
        g_off[i] = off;
        g_cursor[i] = off;
    }
}

// K3: scatter col indices into row buckets.
__global__ void k_fill(const int* __restrict__ row, const int* __restrict__ col, int E) {
    int e = blockIdx.x * blockDim.x + threadIdx.x;
    if (e >= E) return;
    int p = atomicAdd(&g_cursor[row[e]], 1);
    g_adj[p] = col[e];
}

// ---------------------------------------------------------------------------
// K4: node projections. h_q = x@Wq.T, k_act = leaky(x@Wk.T), h_proj = x@Wl.T + bl.
__global__ void __launch_bounds__(128) k_proj(
    const float* __restrict__ x, const float* __restrict__ Wq,
    const float* __restrict__ Wk, const float* __restrict__ Wl,
    const float* __restrict__ bl, int N)
{
    __shared__ float xs[TILE * 132];
    int node0 = blockIdx.x * TILE;
    int tid = threadIdx.x;

    for (int i = tid; i < TILE * 32; i += 128) {
        int n = i >> 5, c = i & 31;
        float4 v = make_float4(0.f, 0.f, 0.f, 0.f);
        if (node0 + n < N)
            v = reinterpret_cast<const float4*>(x)[(size_t)(node0 + n) * 32 + c];
        *reinterpret_cast<float4*>(&xs[n * 132 + c * 4]) = v;
    }
    __syncthreads();

    int d = tid;
    float acc[TILE];
#pragma unroll
    for (int n = 0; n < TILE; n++) acc[n] = 0.f;
    const float4* Wl4 = reinterpret_cast<const float4*>(Wl);
    for (int k4 = 0; k4 < 32; k4++) {
        float4 w = Wl4[d * 32 + k4];
#pragma unroll
        for (int n = 0; n < TILE; n++) {
            float4 xv = *reinterpret_cast<const float4*>(&xs[n * 132 + k4 * 4]);
            acc[n] += w.x * xv.x + w.y * xv.y + w.z * xv.z + w.w * xv.w;
        }
    }
    float b = bl[d];
#pragma unroll
    for (int n = 0; n < TILE; n++) {
        int node = node0 + n;
        if (node < N) g_hproj[(size_t)node * 128 + d] = acc[n] + b;
    }

    {
        int isK = tid >= 64;
        int p = tid & 63;
        int n = p >> 2, h = p & 3;
        const float* W = isK ? Wk : Wq;
        float s = 0.f;
        for (int k = 0; k < 128; k++) s += xs[n * 132 + k] * W[h * 128 + k];
        int node = node0 + n;
        if (node < N) {
            if (isK) g_kact[node * 4 + h] = leaky(s);
            else     g_hq[node * 4 + h]   = s;
        }
    }
}

// ---------------------------------------------------------------------------
// K5: q_agg[r] = sum over incoming edges of h_q[col]. One warp per node.
__global__ void __launch_bounds__(256) k_node_qagg(int N) {
    int node = (blockIdx.x * blockDim.x + threadIdx.x) >> 5;
    int lane = threadIdx.x & 31;
    if (node >= N) return;
    int s0 = g_off[node], s1 = s0 + g_deg[node];
    float a0 = 0.f, a1 = 0.f, a2 = 0.f, a3 = 0.f;
    for (int i = s0 + lane; i < s1; i += 32) {
        int c = g_adj[i];
        float4 v = *reinterpret_cast<const float4*>(&g_hq[c * 4]);
        a0 += v.x; a1 += v.y; a2 += v.z; a3 += v.w;
    }
#pragma unroll
    for (int d = 16; d > 0; d >>= 1) {
        a0 += __shfl_xor_sync(0xffffffffu, a0, d);
        a1 += __shfl_xor_sync(0xffffffffu, a1, d);
        a2 += __shfl_xor_sync(0xffffffffu, a2, d);
        a3 += __shfl_xor_sync(0xffffffffu, a3, d);
    }
    if (lane == 0)
        *reinterpret_cast<float4*>(&g_qagg[node * 4]) = make_float4(a0, a1, a2, a3);
}

// ---------------------------------------------------------------------------
// K6: per-node softmax attention + output. One warp per node.
//   sweep 1: gather q_agg[c] ONCE, compute scores, store to g_sc, track max
//   sweep 2: stream scores back (same-lane addresses), exp, sum, overwrite e
//   sweep 3: stream e, alpha = 0.25*dot(e, inv_t), broadcast + h_proj FMA
// Only 4 exps/edge total; one random q_agg gather pass instead of three.
__global__ void __launch_bounds__(256) k_node_out(float* __restrict__ out, int N) {
    int node = (blockIdx.x * blockDim.x + threadIdx.x) >> 5;
    int lane = threadIdx.x & 31;
    if (node >= N) return;
    int s0 = g_off[node], s1 = s0 + g_deg[node];

    float4 kv = *reinterpret_cast<const float4*>(&g_kact[node * 4]);

    // sweep 1: scores + max
    float m0 = -FLT_MAX, m1 = -FLT_MAX, m2 = -FLT_MAX, m3 = -FLT_MAX;
    for (int i = s0 + lane; i < s1; i += 32) {
        int c = g_adj[i];
        float4 q = *reinterpret_cast<const float4*>(&g_qagg[c * 4]);
        float4 s = make_float4(kv.x * q.x, kv.y * q.y, kv.z * q.z, kv.w * q.w);
        g_sc[i] = s;
        m0 = fmaxf(m0, s.x); m1 = fmaxf(m1, s.y);
        m2 = fmaxf(m2, s.z); m3 = fmaxf(m3, s.w);
    }
#pragma unroll
    for (int d = 16; d > 0; d >>= 1) {
        m0 = fmaxf(m0, __shfl_xor_sync(0xffffffffu, m0, d));
        m1 = fmaxf(m1, __shfl_xor_sync(0xffffffffu, m1, d));
        m2 = fmaxf(m2, __shfl_xor_sync(0xffffffffu, m2, d));
        m3 = fmaxf(m3, __shfl_xor_sync(0xffffffffu, m3, d));
    }

    // sweep 2: exp + sum (reads own stores: same-thread RAW, coherent)
    float t0 = 0.f, t1 = 0.f, t2 = 0.f, t3 = 0.f;
    for (int i = s0 + lane; i < s1; i += 32) {
        float4 s = g_sc[i];
        float4 e = make_float4(__expf(s.x - m0), __expf(s.y - m1),
                               __expf(s.z - m2), __expf(s.w - m3));
        g_sc[i] = e;
        t0 += e.x; t1 += e.y; t2 += e.z; t3 += e.w;
    }
#pragma unroll
    for (int d = 16; d > 0; d >>= 1) {
        t0 += __shfl_xor_sync(0xffffffffu, t0, d);
        t1 += __shfl_xor_sync(0xffffffffu, t1, d);
        t2 += __shfl_xor_sync(0xffffffffu, t2, d);
        t3 += __shfl_xor_sync(0xffffffffu, t3, d);
    }
    float i0 = 0.25f / (t0 + 1e-8f);
    float i1 = 0.25f / (t1 + 1e-8f);
    float i2 = 0.25f / (t2 + 1e-8f);
    float i3 = 0.25f / (t3 + 1e-8f);

    // sweep 3: alpha (no exp) + broadcast + coalesced h_proj gather/FMA
    float a0 = 0.f, a1 = 0.f, a2 = 0.f, a3 = 0.f;
    for (int base = s0; base < s1; base += 32) {
        int i = base + lane;
        float alpha = 0.f;
        int c = 0;
        if (i < s1) {
            c = g_adj[i];
            float4 e = g_sc[i];
            alpha = e.x * i0 + e.y * i1 + e.z * i2 + e.w * i3;
        }
        int cnt = min(32, s1 - base);
#pragma unroll 4
        for (int j = 0; j < cnt; j++) {
            float aj = __shfl_sync(0xffffffffu, alpha, j);
            int   cj = __shfl_sync(0xffffffffu, c, j);
            float4 v = *reinterpret_cast<const float4*>(&g_hproj[(size_t)cj * 128 + lane * 4]);
            a0 += aj * v.x; a1 += aj * v.y; a2 += aj * v.z; a3 += aj * v.w;
        }
    }

    float4 r = make_float4(leaky(a0), leaky(a1), leaky(a2), leaky(a3));
    *reinterpret_cast<float4*>(&out[(size_t)node * 128 + lane * 4]) = r;
}

// ---------------------------------------------------------------------------
extern "C" void kernel_launch(void* const* d_in, const int* in_sizes, int n_in,
                              void* d_out, int out_size) {
    const float* x  = (const float*)d_in[0];
    const int*   ei = (const int*)d_in[1];
    const float* Wq = (const float*)d_in[2];
    const float* Wk = (const float*)d_in[3];
    const float* Wl = (const float*)d_in[4];
    const float* bl = (const float*)d_in[5];
    float* out = (float*)d_out;

    int N = in_sizes[0] / 128;
    int E = in_sizes[1] / 2;
    const int* row = ei;
    const int* col = ei + E;

    int eb = (E + 255) / 256;
    int nb = (N + 255) / 256;

    k_init<<<nb, 256>>>(N);
    k_proj<<<(N + TILE - 1) / TILE, 128>>>(x, Wq, Wk, Wl, bl, N);
    k_deg<<<eb, 256>>>(row, E);
    k_off<<<nb, 256>>>(N);
    k_fill<<<eb, 256>>>(row, col, E);

    int wb = (int)(((long long)N * 32 + 255) / 256);
    k_node_qagg<<<wb, 256>>>(N);
    k_node_out<<<wb, 256>>>(out, N);
}